// round 13
// baseline (speedup 1.0000x reference)
#include <cuda_runtime.h>
#include <cuda_fp16.h>
#include <math.h>

// Problem dims
#define BB   4
#define SS   2048
#define FF   512
#define HH   8
#define DKK  64
#define DVV  64
#define FILT 512

// Scratch (allocation-free rule: __device__ globals) — fp16 intermediates
__device__ __half g_Qh[BB*HH*SS*DKK];
__device__ __half g_Kh[BB*HH*SS*DKK];
__device__ __half g_Vh[BB*HH*SS*DVV];
__device__ __half g_atth[BB*SS*HH*DVV];
// fp16 copies of inputs (converted once per call)
__device__ __half g_Xqh[BB*SS*FF];
__device__ __half g_Xkh[BB*SS*FF];
__device__ __half g_Xvh[BB*SS*FF];
__device__ __half g_Wqh[HH*FF*DKK];
__device__ __half g_Wkh[HH*FF*DKK];
__device__ __half g_Wvh[HH*FF*DVV];
__device__ __half g_Woh[FF*FILT];

// ---------------------------------------------------------------------------
// helpers
// ---------------------------------------------------------------------------
__device__ __forceinline__ float ex2(float x) {      // MUFU pipe exp2
    float r;
    asm("ex2.approx.ftz.f32 %0, %1;" : "=f"(r) : "f"(x));
    return r;
}

__device__ __forceinline__ void mma_f16(float& d0, float& d1, float& d2, float& d3,
                                        unsigned a0, unsigned a1, unsigned a2, unsigned a3,
                                        unsigned b0, unsigned b1) {
    asm("mma.sync.aligned.m16n8k16.row.col.f32.f16.f16.f32 "
        "{%0,%1,%2,%3}, {%4,%5,%6,%7}, {%8,%9}, {%0,%1,%2,%3};"
        : "+f"(d0), "+f"(d1), "+f"(d2), "+f"(d3)
        : "r"(a0), "r"(a1), "r"(a2), "r"(a3), "r"(b0), "r"(b1));
}

__device__ __forceinline__ void ldsm_x4(unsigned& r0, unsigned& r1, unsigned& r2, unsigned& r3,
                                        unsigned addr) {
    asm volatile("ldmatrix.sync.aligned.m8n8.x4.shared.b16 {%0,%1,%2,%3}, [%4];"
                 : "=r"(r0), "=r"(r1), "=r"(r2), "=r"(r3) : "r"(addr));
}
__device__ __forceinline__ void ldsm_x4_trans(unsigned& r0, unsigned& r1, unsigned& r2, unsigned& r3,
                                              unsigned addr) {
    asm volatile("ldmatrix.sync.aligned.m8n8.x4.trans.shared.b16 {%0,%1,%2,%3}, [%4];"
                 : "=r"(r0), "=r"(r1), "=r"(r2), "=r"(r3) : "r"(addr));
}

__device__ __forceinline__ unsigned h2pack(float a, float b) {
    __half2 hv = __float22half2_rn(make_float2(a, b));
    return *reinterpret_cast<unsigned*>(&hv);
}

__device__ __forceinline__ unsigned cvt2h(float lo, float hi) {  // {hi:lo} fp16x2
    unsigned r;
    asm("cvt.rn.f16x2.f32 %0, %1, %2;" : "=r"(r) : "f"(hi), "f"(lo));
    return r;
}

__device__ __forceinline__ unsigned smem_u32(const void* p) {
    return (unsigned)__cvta_generic_to_shared(p);
}

__device__ __forceinline__ void cp16(unsigned dst, const void* src) {
    asm volatile("cp.async.cg.shared.global [%0], [%1], 16;" :: "r"(dst), "l"(src));
}
__device__ __forceinline__ void cp_commit() { asm volatile("cp.async.commit_group;"); }
__device__ __forceinline__ void cp_wait0()  { asm volatile("cp.async.wait_group 0;"); }

// ---------------------------------------------------------------------------
// One-shot fp32->fp16 conversion of all inputs. grid.y selects the array.
// ---------------------------------------------------------------------------
__global__ __launch_bounds__(256) void cvt_kernel(
    const float* __restrict__ xq, const float* __restrict__ xk, const float* __restrict__ xv,
    const float* __restrict__ wq, const float* __restrict__ wk, const float* __restrict__ wv,
    const float* __restrict__ wo,
    __half* __restrict__ dxq, __half* __restrict__ dxk, __half* __restrict__ dxv,
    __half* __restrict__ dwq, __half* __restrict__ dwk, __half* __restrict__ dwv,
    __half* __restrict__ dwo)
{
    const int a = blockIdx.y;
    const float* src; __half* dst; int n;
    switch (a) {
        case 0: src = xq; dst = dxq; n = BB*SS*FF;   break;
        case 1: src = xk; dst = dxk; n = BB*SS*FF;   break;
        case 2: src = xv; dst = dxv; n = BB*SS*FF;   break;
        case 3: src = wq; dst = dwq; n = HH*FF*DKK;  break;
        case 4: src = wk; dst = dwk; n = HH*FF*DKK;  break;
        case 5: src = wv; dst = dwv; n = HH*FF*DVV;  break;
        default: src = wo; dst = dwo; n = FF*FILT;   break;
    }
    int i = (blockIdx.x * 256 + threadIdx.x) * 4;
    if (i < n) {
        float4 v = *reinterpret_cast<const float4*>(src + i);
        uint2 hv;
        hv.x = h2pack(v.x, v.y);
        hv.y = h2pack(v.z, v.w);
        *reinterpret_cast<uint2*>(dst + i) = hv;
    }
}

// ---------------------------------------------------------------------------
// Shared GEMM mainloop: 128x64 tile, BK=64, cp.async double-buffered fp16.
// ---------------------------------------------------------------------------
#define ABYTES (128 * 72 * 2)
#define BBYTES (64 * 72 * 2)
#define GEMM_SMEM (2 * ABYTES + 2 * BBYTES)

__device__ __forceinline__ void gemm_mainloop_h(
    const __half* __restrict__ Abase, int lda,
    const __half* __restrict__ Bbase, int ldb,
    float acc[8][4], unsigned smem_base, int tid)
{
    const int lane = tid & 31;
    const int w    = tid >> 5;
    const unsigned sA_base = smem_base;
    const unsigned sB_base = smem_base + 2 * ABYTES;

    const int ra  = tid >> 2;
    const int ca  = (tid & 3) * 16;
    const int rb  = tid >> 3;
    const int cb  = (tid & 7) * 8;

    {
        cp16(sA_base + (unsigned)(ra * 72 + ca) * 2u,        Abase + (size_t)ra * lda + ca);
        cp16(sA_base + (unsigned)(ra * 72 + ca + 8) * 2u,    Abase + (size_t)ra * lda + ca + 8);
        cp16(sA_base + (unsigned)((ra + 64) * 72 + ca) * 2u,     Abase + (size_t)(ra + 64) * lda + ca);
        cp16(sA_base + (unsigned)((ra + 64) * 72 + ca + 8) * 2u, Abase + (size_t)(ra + 64) * lda + ca + 8);
        cp16(sB_base + (unsigned)(rb * 72 + cb) * 2u,        Bbase + (size_t)rb * ldb + cb);
        cp16(sB_base + (unsigned)((rb + 32) * 72 + cb) * 2u, Bbase + (size_t)(rb + 32) * ldb + cb);
        cp_commit();
    }

    for (int kt = 0, it = 0; kt < FF; kt += 64, it++) {
        cp_wait0();
        __syncthreads();

        if (kt + 64 < FF) {
            unsigned ao = (unsigned)((it + 1) & 1) * ABYTES;
            unsigned bo = (unsigned)((it + 1) & 1) * BBYTES;
            const __half* An = Abase + kt + 64;
            const __half* Bn = Bbase + (size_t)(kt + 64) * ldb;
            cp16(sA_base + ao + (unsigned)(ra * 72 + ca) * 2u,        An + (size_t)ra * lda + ca);
            cp16(sA_base + ao + (unsigned)(ra * 72 + ca + 8) * 2u,    An + (size_t)ra * lda + ca + 8);
            cp16(sA_base + ao + (unsigned)((ra + 64) * 72 + ca) * 2u,     An + (size_t)(ra + 64) * lda + ca);
            cp16(sA_base + ao + (unsigned)((ra + 64) * 72 + ca + 8) * 2u, An + (size_t)(ra + 64) * lda + ca + 8);
            cp16(sB_base + bo + (unsigned)(rb * 72 + cb) * 2u,        Bn + (size_t)rb * ldb + cb);
            cp16(sB_base + bo + (unsigned)((rb + 32) * 72 + cb) * 2u, Bn + (size_t)(rb + 32) * ldb + cb);
            cp_commit();
        }

        const unsigned abase = sA_base + (unsigned)(it & 1) * ABYTES;
        const unsigned bbase = sB_base + (unsigned)(it & 1) * BBYTES;

        #pragma unroll
        for (int kk = 0; kk < 4; kk++) {
            int arow = w * 16 + ((lane >> 3) & 1) * 8 + (lane & 7);
            int acol = kk * 16 + (lane >> 4) * 8;
            unsigned a0, a1, a2, a3;
            ldsm_x4(a0, a1, a2, a3, abase + (unsigned)(arow * 72 + acol) * 2u);

            #pragma unroll
            for (int ntp = 0; ntp < 4; ntp++) {
                int brow = kk * 16 + ((lane >> 3) & 1) * 8 + (lane & 7);
                int bcol = ntp * 16 + (lane >> 4) * 8;
                unsigned b0, b1, b2, b3;
                ldsm_x4_trans(b0, b1, b2, b3, bbase + (unsigned)(brow * 72 + bcol) * 2u);
                mma_f16(acc[2*ntp][0], acc[2*ntp][1], acc[2*ntp][2], acc[2*ntp][3],
                        a0, a1, a2, a3, b0, b1);
                mma_f16(acc[2*ntp+1][0], acc[2*ntp+1][1], acc[2*ntp+1][2], acc[2*ntp+1][3],
                        a0, a1, a2, a3, b2, b3);
            }
        }
    }
}

// ---------------------------------------------------------------------------
// Merged projection (Q/K/V), fp16 in/out, pipelined mainloop.
// ---------------------------------------------------------------------------
__global__ __launch_bounds__(256, 2) void proj_h3_kernel(
    const float* __restrict__ bq, const float* __restrict__ bk, const float* __restrict__ bv,
    float qscale)
{
    extern __shared__ __half smdyn[];
    const int b    = blockIdx.z;
    const int m    = blockIdx.y >> 3;
    const int h    = blockIdx.y & 7;
    const int row0 = blockIdx.x * 128;

    const __half* X    = (m == 0) ? g_Xqh : (m == 1) ? g_Xkh : g_Xvh;
    const __half* W    = (m == 0) ? g_Wqh : (m == 1) ? g_Wkh : g_Wvh;
    const float* bias  = (m == 0) ? bq : (m == 1) ? bk : bv;
    __half* outh       = (m == 0) ? g_Qh : (m == 1) ? g_Kh : g_Vh;
    const float scale  = (m == 0) ? qscale : 1.0f;

    const int tid  = threadIdx.x;
    const int w    = tid >> 5;
    const int lane = tid & 31;
    const int g    = lane >> 2;
    const int t    = lane & 3;

    float acc[8][4];
    #pragma unroll
    for (int nt = 0; nt < 8; nt++)
        #pragma unroll
        for (int j = 0; j < 4; j++) acc[nt][j] = 0.f;

    gemm_mainloop_h(X + ((size_t)b * SS + row0) * FF, FF,
                    W + (size_t)h * FF * DKK, DKK,
                    acc, smem_u32(smdyn), tid);

    const float* bh = bias + h * DKK;
    __half* Oh = outh + (((size_t)b * HH + h) * SS + row0) * DKK;
    int r0 = w * 16 + g;
    #pragma unroll
    for (int nt = 0; nt < 8; nt++) {
        int c = nt * 8 + 2 * t;
        float b0 = bh[c], b1 = bh[c + 1];
        unsigned v0 = h2pack((acc[nt][0] + b0) * scale, (acc[nt][1] + b1) * scale);
        unsigned v1 = h2pack((acc[nt][2] + b0) * scale, (acc[nt][3] + b1) * scale);
        *reinterpret_cast<unsigned*>(Oh + (size_t)r0 * DKK + c) = v0;
        *reinterpret_cast<unsigned*>(Oh + (size_t)(r0 + 8) * DKK + c) = v1;
    }
}

// ---------------------------------------------------------------------------
// Output GEMM, fp16 A and Wo, pipelined mainloop, fp32 out.
// ---------------------------------------------------------------------------
__global__ __launch_bounds__(256, 2) void out_h_kernel(
    const float* __restrict__ bo,
    float* __restrict__ out)
{
    extern __shared__ __half smdyn[];
    const int row0 = blockIdx.x * 128;
    const int col0 = blockIdx.y * 64;

    const int tid  = threadIdx.x;
    const int w    = tid >> 5;
    const int lane = tid & 31;
    const int g    = lane >> 2;
    const int t    = lane & 3;

    float acc[8][4];
    #pragma unroll
    for (int nt = 0; nt < 8; nt++)
        #pragma unroll
        for (int j = 0; j < 4; j++) acc[nt][j] = 0.f;

    gemm_mainloop_h(g_atth + (size_t)row0 * FF, FF,
                    g_Woh + col0, FILT,
                    acc, smem_u32(smdyn), tid);

    int r0 = row0 + w * 16 + g;
    #pragma unroll
    for (int nt = 0; nt < 8; nt++) {
        int c = col0 + nt * 8 + 2 * t;
        float b0 = bo[c], b1 = bo[c + 1];
        float2 v0 = make_float2(acc[nt][0] + b0, acc[nt][1] + b1);
        float2 v1 = make_float2(acc[nt][2] + b0, acc[nt][3] + b1);
        *reinterpret_cast<float2*>(out + (size_t)r0 * FILT + c) = v0;
        *reinterpret_cast<float2*>(out + (size_t)(r0 + 8) * FILT + c) = v1;
    }
}

// ---------------------------------------------------------------------------
// Flash attention: fp16 mma, MUFU ex2 softmax, l via ones-MMA,
// cp.async double-buffered K/V, uniform rescale-skip.
// ---------------------------------------------------------------------------
#define KVBUF (64 * 72)
__global__ __launch_bounds__(256, 2) void attn_mma_kernel()
{
    const int b  = blockIdx.z;
    const int h  = blockIdx.y;
    const int q0 = blockIdx.x * 128;

    const int tid  = threadIdx.x;
    const int w    = tid >> 5;
    const int lane = tid & 31;
    const int g    = lane >> 2;
    const int t    = lane & 3;

    __shared__ __half sK[2][64][72];
    __shared__ __half sV[2][64][72];

    const __half* Qb = g_Qh + (((size_t)b * HH + h) * SS + q0 + w * 16) * DKK;
    const __half* Kb = g_Kh + ((size_t)b * HH + h) * SS * DKK;
    const __half* Vb = g_Vh + ((size_t)b * HH + h) * SS * DVV;

    const unsigned ONESH = 0x3C003C00u;

    unsigned qa[4][4];
    #pragma unroll
    for (int kk = 0; kk < 4; kk++) {
        const __half* r0p = Qb + (size_t)g * DKK + kk * 16;
        const __half* r1p = Qb + (size_t)(g + 8) * DKK + kk * 16;
        qa[kk][0] = *reinterpret_cast<const unsigned*>(r0p + 2 * t);
        qa[kk][1] = *reinterpret_cast<const unsigned*>(r1p + 2 * t);
        qa[kk][2] = *reinterpret_cast<const unsigned*>(r0p + 2 * t + 8);
        qa[kk][3] = *reinterpret_cast<const unsigned*>(r1p + 2 * t + 8);
    }

    float o[8][4];
    #pragma unroll
    for (int vt = 0; vt < 8; vt++)
        #pragma unroll
        for (int j = 0; j < 4; j++) o[vt][j] = 0.f;

    float la[4] = {0.f, 0.f, 0.f, 0.f};
    float m0 = -1e30f, m1 = -1e30f;

    const unsigned sK_base = smem_u32(&sK[0][0][0]);
    const unsigned sV_base = smem_u32(&sV[0][0][0]);

    const int r_a  = tid >> 3;
    const int c8_a = (tid & 7) * 8;
    const int r_b  = r_a + 32;

    {
        cp16(sK_base + (unsigned)(r_a * 72 + c8_a) * 2u, Kb + (size_t)r_a * DKK + c8_a);
        cp16(sK_base + (unsigned)(r_b * 72 + c8_a) * 2u, Kb + (size_t)r_b * DKK + c8_a);
        cp16(sV_base + (unsigned)(r_a * 72 + c8_a) * 2u, Vb + (size_t)r_a * DVV + c8_a);
        cp16(sV_base + (unsigned)(r_b * 72 + c8_a) * 2u, Vb + (size_t)r_b * DVV + c8_a);
        cp_commit();
    }

    for (int kt = 0, it = 0; kt < SS; kt += 64, it++) {
        cp_wait0();
        __syncthreads();

        if (kt + 64 < SS) {
            unsigned nb = (unsigned)((it + 1) & 1) * (KVBUF * 2u);
            const __half* Kn = Kb + (size_t)(kt + 64) * DKK;
            const __half* Vn = Vb + (size_t)(kt + 64) * DVV;
            cp16(sK_base + nb + (unsigned)(r_a * 72 + c8_a) * 2u, Kn + (size_t)r_a * DKK + c8_a);
            cp16(sK_base + nb + (unsigned)(r_b * 72 + c8_a) * 2u, Kn + (size_t)r_b * DKK + c8_a);
            cp16(sV_base + nb + (unsigned)(r_a * 72 + c8_a) * 2u, Vn + (size_t)r_a * DVV + c8_a);
            cp16(sV_base + nb + (unsigned)(r_b * 72 + c8_a) * 2u, Vn + (size_t)r_b * DVV + c8_a);
            cp_commit();
        }

        const unsigned kbase = sK_base + (unsigned)(it & 1) * (KVBUF * 2u);
        const unsigned vbase = sV_base + (unsigned)(it & 1) * (KVBUF * 2u);

        // ---- S = Q @ K^T ----
        float s[8][4];
        #pragma unroll
        for (int nt = 0; nt < 8; nt++)
            #pragma unroll
            for (int j = 0; j < 4; j++) s[nt][j] = 0.f;

        #pragma unroll
        for (int kk = 0; kk < 4; kk++) {
            #pragma unroll
            for (int ntp = 0; ntp < 4; ntp++) {
                int mrow = (2 * ntp + (lane >> 4)) * 8 + (lane & 7);
                int mcol = kk * 16 + ((lane >> 3) & 1) * 8;
                unsigned addr = kbase + (unsigned)(mrow * 72 + mcol) * 2u;
                unsigned b0, b1, b2, b3;
                ldsm_x4(b0, b1, b2, b3, addr);
                mma_f16(s[2*ntp][0], s[2*ntp][1], s[2*ntp][2], s[2*ntp][3],
                        qa[kk][0], qa[kk][1], qa[kk][2], qa[kk][3], b0, b1);
                mma_f16(s[2*ntp+1][0], s[2*ntp+1][1], s[2*ntp+1][2], s[2*ntp+1][3],
                        qa[kk][0], qa[kk][1], qa[kk][2], qa[kk][3], b2, b3);
            }
        }

        // ---- online softmax (base-2), MUFU ex2 ----
        float rmax0 = -1e30f, rmax1 = -1e30f;
        #pragma unroll
        for (int nt = 0; nt < 8; nt++) {
            rmax0 = fmaxf(rmax0, fmaxf(s[nt][0], s[nt][1]));
            rmax1 = fmaxf(rmax1, fmaxf(s[nt][2], s[nt][3]));
        }
        rmax0 = fmaxf(rmax0, __shfl_xor_sync(0xffffffffu, rmax0, 1));
        rmax0 = fmaxf(rmax0, __shfl_xor_sync(0xffffffffu, rmax0, 2));
        rmax1 = fmaxf(rmax1, __shfl_xor_sync(0xffffffffu, rmax1, 1));
        rmax1 = fmaxf(rmax1, __shfl_xor_sync(0xffffffffu, rmax1, 2));

        // uniform skip: rescale only if any row in this warp raised its max
        bool upd = __any_sync(0xffffffffu, (rmax0 > m0) || (rmax1 > m1));
        if (upd) {
            float nm0 = fmaxf(m0, rmax0);
            float nm1 = fmaxf(m1, rmax1);
            float al0 = ex2(m0 - nm0);   // ex2(-huge) -> 0 handles first tile
            float al1 = ex2(m1 - nm1);
            m0 = nm0; m1 = nm1;
            #pragma unroll
            for (int vt = 0; vt < 8; vt++) {
                o[vt][0] *= al0; o[vt][1] *= al0;
                o[vt][2] *= al1; o[vt][3] *= al1;
            }
            la[0] *= al0; la[1] *= al0;
            la[2] *= al1; la[3] *= al1;
        }

        unsigned ph[8][2];
        #pragma unroll
        for (int nt = 0; nt < 8; nt++) {
            float p0 = ex2(s[nt][0] - m0);
            float p1 = ex2(s[nt][1] - m0);
            float p2 = ex2(s[nt][2] - m1);
            float p3 = ex2(s[nt][3] - m1);
            ph[nt][0] = cvt2h(p0, p1);
            ph[nt][1] = cvt2h(p2, p3);
        }

        // ---- O += P @ V, l += P @ 1 ----
        #pragma unroll
        for (int m = 0; m < 4; m++) {
            unsigned pa0 = ph[2*m][0];
            unsigned pa1 = ph[2*m][1];
            unsigned pa2 = ph[2*m+1][0];
            unsigned pa3 = ph[2*m+1][1];
            mma_f16(la[0], la[1], la[2], la[3], pa0, pa1, pa2, pa3, ONESH, ONESH);
            #pragma unroll
            for (int vtp = 0; vtp < 4; vtp++) {
                int mrow = 16 * m + ((lane >> 3) & 1) * 8 + (lane & 7);
                int mcol = vtp * 16 + (lane >> 4) * 8;
                unsigned addr = vbase + (unsigned)(mrow * 72 + mcol) * 2u;
                unsigned b0, b1, b2, b3;
                ldsm_x4_trans(b0, b1, b2, b3, addr);
                mma_f16(o[2*vtp][0], o[2*vtp][1], o[2*vtp][2], o[2*vtp][3],
                        pa0, pa1, pa2, pa3, b0, b1);
                mma_f16(o[2*vtp+1][0], o[2*vtp+1][1], o[2*vtp+1][2], o[2*vtp+1][3],
                        pa0, pa1, pa2, pa3, b2, b3);
            }
        }
    }

    float inv0 = 1.f / la[0];
    float inv1 = 1.f / la[2];
    int r0 = q0 + w * 16 + g;
    int r1 = r0 + 8;
    #pragma unroll
    for (int vt = 0; vt < 8; vt++) {
        unsigned v0 = h2pack(o[vt][0] * inv0, o[vt][1] * inv0);
        unsigned v1 = h2pack(o[vt][2] * inv1, o[vt][3] * inv1);
        *reinterpret_cast<unsigned*>(g_atth + ((size_t)b * SS + r0) * (HH * DVV) + h * DVV + vt * 8 + 2 * t) = v0;
        *reinterpret_cast<unsigned*>(g_atth + ((size_t)b * SS + r1) * (HH * DVV) + h * DVV + vt * 8 + 2 * t) = v1;
    }
}

// ---------------------------------------------------------------------------
extern "C" void kernel_launch(void* const* d_in, const int* in_sizes, int n_in,
                              void* d_out, int out_size)
{
    const float* x_q = (const float*)d_in[0];
    const float* x_k = (const float*)d_in[1];
    const float* x_v = (const float*)d_in[2];
    const float* Wq  = (const float*)d_in[3];
    const float* bq  = (const float*)d_in[4];
    const float* Wk  = (const float*)d_in[5];
    const float* bk  = (const float*)d_in[6];
    const float* Wv  = (const float*)d_in[7];
    const float* bv  = (const float*)d_in[8];
    const float* Wo  = (const float*)d_in[9];
    const float* bo  = (const float*)d_in[10];
    float* out = (float*)d_out;

    __half *Xqp, *Xkp, *Xvp, *Wqp, *Wkp, *Wvp, *Wop;
    cudaGetSymbolAddress((void**)&Xqp, g_Xqh);
    cudaGetSymbolAddress((void**)&Xkp, g_Xkh);
    cudaGetSymbolAddress((void**)&Xvp, g_Xvh);
    cudaGetSymbolAddress((void**)&Wqp, g_Wqh);
    cudaGetSymbolAddress((void**)&Wkp, g_Wkh);
    cudaGetSymbolAddress((void**)&Wvp, g_Wvh);
    cudaGetSymbolAddress((void**)&Wop, g_Woh);

    static int smem_set = 0;
    if (!smem_set) {
        cudaFuncSetAttribute(proj_h3_kernel, cudaFuncAttributeMaxDynamicSharedMemorySize, GEMM_SMEM);
        cudaFuncSetAttribute(out_h_kernel,  cudaFuncAttributeMaxDynamicSharedMemorySize, GEMM_SMEM);
        smem_set = 1;
    }

    const float QS = 0.125f * 1.4426950408889634f;  // 1/sqrt(dk) * log2(e)

    dim3 gcvt((BB * SS * FF / 4 + 255) / 256, 7);
    cvt_kernel<<<gcvt, 256>>>(x_q, x_k, x_v, Wq, Wk, Wv, Wo,
                              Xqp, Xkp, Xvp, Wqp, Wkp, Wvp, Wop);

    dim3 gproj(SS / 128, 3 * HH, BB);
    proj_h3_kernel<<<gproj, 256, GEMM_SMEM>>>(bq, bk, bv, QS);

    dim3 gattn(SS / 128, HH, BB);
    attn_mma_kernel<<<gattn, 256>>>();

    dim3 gout((BB * SS) / 128, FILT / 64);
    out_h_kernel<<<gout, 256, GEMM_SMEM>>>(bo, out);
}